// round 1
// baseline (speedup 1.0000x reference)
#include <cuda_runtime.h>

// GCA neural-cellular-automaton step, fully fused, fp32 with packed f32x2 FMA.
// B=16, C=16, H=256, W=256, HID=128, OUT_C=13.
// Each thread computes 2 horizontally-adjacent pixels packed into f32x2 lanes.

#define Bz   16
#define Cz   16
#define Hz   256
#define Wz   256
#define HID  128
#define OUTC 13
#define PCH  48                      // perception channels: 16 id + 16 gx + 16 gy
#define NPIX (Bz * Hz * Wz)          // 1,048,576
#define NTHR (NPIX / 2)              // 524,288 threads (2 px each)
#define TPB  384

typedef unsigned long long ull;

__device__ __forceinline__ ull ffma2(ull a, ull b, ull c) {
    ull d;
    asm("fma.rn.f32x2 %0, %1, %2, %3;" : "=l"(d) : "l"(a), "l"(b), "l"(c));
    return d;
}
__device__ __forceinline__ ull pack2(float lo, float hi) {
    ull r;
    asm("mov.b64 %0, {%1, %2};" : "=l"(r) : "f"(lo), "f"(hi));
    return r;
}
__device__ __forceinline__ float2 unpack2(ull v) {
    float2 r;
    asm("mov.b64 {%0, %1}, %2;" : "=f"(r.x), "=f"(r.y) : "l"(v));
    return r;
}
__device__ __forceinline__ ull dup2(float v) { return pack2(v, v); }
__device__ __forceinline__ ull relu2(ull h) {
    float2 v = unpack2(h);
    v.x = fmaxf(v.x, 0.0f);
    v.y = fmaxf(v.y, 0.0f);
    return pack2(v.x, v.y);
}

// SMEM layout (ulonglong2 = 16B quads):
//   w1q[c*64 + o2] = (dup w1[2o2][c], dup w1[2o2+1][c])      48*64 quads
//   w2q[j*64 + o2] = (dup w2[j][2o2], dup w2[j][2o2+1])      13*64 quads
//   b1q[o2]        = (dup b1[2o2],    dup b1[2o2+1])            64 quads
#define NW1Q (PCH * 64)
#define NW2Q (OUTC * 64)
#define NB1Q 64
#define SMEM_BYTES ((NW1Q + NW2Q + NB1Q) * 16)

__global__ __launch_bounds__(TPB, 1)
void GCA_kernel(const float* __restrict__ in, const float* __restrict__ w1,
                const float* __restrict__ b1, const float* __restrict__ w2,
                float* __restrict__ out)
{
    extern __shared__ ull sm_raw[];
    ulonglong2* s_w1 = reinterpret_cast<ulonglong2*>(sm_raw);
    ulonglong2* s_w2 = s_w1 + NW1Q;
    ulonglong2* s_b1 = s_w2 + NW2Q;

    const int tid = threadIdx.x;

    // ---- stage duplicated weight quads into shared memory ----
    for (int i = tid; i < NW1Q; i += TPB) {
        int c = i >> 6, o2 = i & 63;
        float wa = w1[(2 * o2) * PCH + c];
        float wb = w1[(2 * o2 + 1) * PCH + c];
        s_w1[i] = make_ulonglong2(dup2(wa), dup2(wb));
    }
    for (int i = tid; i < NW2Q; i += TPB) {
        int j = i >> 6, o2 = i & 63;
        s_w2[i] = make_ulonglong2(dup2(w2[j * HID + 2 * o2]),
                                  dup2(w2[j * HID + 2 * o2 + 1]));
    }
    if (tid < NB1Q)
        s_b1[tid] = make_ulonglong2(dup2(b1[2 * tid]), dup2(b1[2 * tid + 1]));
    __syncthreads();

    const int t = blockIdx.x * TPB + tid;
    if (t >= NTHR) return;

    const int p  = t << 1;            // linear pixel index of left pixel (even x)
    const int bc = p >> 16;           // batch index
    const int y  = (p >> 8) & 255;
    const int x0 = p & 255;           // even, so x0+1 never wraps

    const int xm = (x0 - 1) & 255;
    const int x2 = (x0 + 2) & 255;
    const int rm = ((y - 1) & 255) << 8;
    const int r0 = y << 8;
    const int rp = ((y + 1) & 255) << 8;

    const float* base = in + ((size_t)bc << 20);   // bc * C*H*W

    // ---- perception: 48 packed (pixel0, pixel1) pairs ----
    ull pp[PCH];
#pragma unroll
    for (int ch = 0; ch < Cz; ++ch) {
        const float* pc = base + (ch << 16);
        float2 a12 = *reinterpret_cast<const float2*>(pc + rm + x0);
        float2 b12 = *reinterpret_cast<const float2*>(pc + r0 + x0);
        float2 c12 = *reinterpret_cast<const float2*>(pc + rp + x0);
        float a0 = pc[rm + xm], a3 = pc[rm + x2];
        float b0 = pc[r0 + xm], b3 = pc[r0 + x2];
        float c0 = pc[rp + xm], c3 = pc[rp + x2];

        // sobel-x (cross-correlation with [[-1,0,1],[-2,0,2],[-1,0,1]])
        float gx0 = (a12.y - a0) + 2.0f * (b12.y - b0) + (c12.y - c0);
        float gx1 = (a3 - a12.x) + 2.0f * (b3 - b12.x) + (c3 - c12.x);
        // sobel-y (transpose)
        float gy0 = (c0 + 2.0f * c12.x + c12.y) - (a0 + 2.0f * a12.x + a12.y);
        float gy1 = (c12.x + 2.0f * c12.y + c3) - (a12.x + 2.0f * a12.y + a3);

        pp[ch]          = pack2(b12.x, b12.y);
        pp[Cz + ch]     = pack2(gx0, gx1);
        pp[2 * Cz + ch] = pack2(gy0, gy1);
    }

    // ---- fused MLP: 48 -> 128 (ReLU) -> 13, hidden never materialized ----
    ull ds[OUTC];
#pragma unroll
    for (int j = 0; j < OUTC; ++j) ds[j] = 0ull;   // bit pattern of (0.f, 0.f)

#pragma unroll 1
    for (int o2 = 0; o2 < 64; ++o2) {              // two hidden units per iter
        ulonglong2 bb = s_b1[o2];
        ull h0 = bb.x, h1 = bb.y;
        const ulonglong2* wrow = s_w1 + o2;
#pragma unroll
        for (int c = 0; c < PCH; ++c) {
            ulonglong2 w = wrow[c * 64];           // one LDS.128 -> 2 FFMA2
            h0 = ffma2(w.x, pp[c], h0);
            h1 = ffma2(w.y, pp[c], h1);
        }
        h0 = relu2(h0);
        h1 = relu2(h1);
        const ulonglong2* w2row = s_w2 + o2;
#pragma unroll
        for (int j = 0; j < OUTC; ++j) {
            ulonglong2 w = w2row[j * 64];
            ds[j] = ffma2(w.x, h0, ds[j]);
            ds[j] = ffma2(w.y, h1, ds[j]);
        }
    }

    // ---- residual write: ch 0..2 copy, ch 3..15 add ds ----
    float* ob = out + ((size_t)bc << 20) + r0 + x0;
#pragma unroll
    for (int ch = 0; ch < 3; ++ch) {
        float2 v = unpack2(pp[ch]);
        *reinterpret_cast<float2*>(ob + (ch << 16)) = v;
    }
#pragma unroll
    for (int ch = 3; ch < Cz; ++ch) {
        float2 v = unpack2(pp[ch]);
        float2 d = unpack2(ds[ch - 3]);
        v.x += d.x;
        v.y += d.y;
        *reinterpret_cast<float2*>(ob + (ch << 16)) = v;
    }
}

extern "C" void kernel_launch(void* const* d_in, const int* in_sizes, int n_in,
                              void* d_out, int out_size)
{
    const float* in = (const float*)d_in[0];
    const float* w1 = (const float*)d_in[1];
    const float* b1 = (const float*)d_in[2];
    const float* w2 = (const float*)d_in[3];
    float* out = (float*)d_out;

    cudaFuncSetAttribute(GCA_kernel,
                         cudaFuncAttributeMaxDynamicSharedMemorySize, SMEM_BYTES);
    const int grid = (NTHR + TPB - 1) / TPB;       // 1366 blocks
    GCA_kernel<<<grid, TPB, SMEM_BYTES>>>(in, w1, b1, w2, out);
}

// round 3
// speedup vs baseline: 2.9393x; 2.9393x over previous
#include <cuda_runtime.h>
#include <cuda_bf16.h>
#include <cstdint>

// Fused GCA step via warp-level bf16 MMA (mma.sync m16n8k16 — base-target PTX).
// B=16,C=16,H=256,W=256, HID=128, OUT_C=13, perception K=48.
#define Cz     16
#define HID    128
#define OUTC   13
#define PCH    48
#define TILE   256
#define NTILES 4096        // 2^20 px / 256
#define TPB    128
#define GRID   296

// ---- shared memory (bytes) ----
#define SM_P   0            // P[48 ch][256 px] bf16 swizzled, 512B rows  -> 24576
#define SM_H   24576        // H[128 hid][256 px] bf16 swizzled           -> 65536
#define SM_DS  90112        // ds[16 ch][256 px] fp32 swizzled            -> 16384
#define SM_TOT 106496
// weight staging (inside H region, consumed before first H write)
#define SM_W1T (SM_H)           // W1t[48 k][128 n] bf16, 256B rows (12288)
#define SM_W2T (SM_H + 12288)   // W2t[128 k][16 n] bf16, 32B rows  (4096)

typedef unsigned int u32;

__device__ __forceinline__ u32 smem_u32(const void* p) {
    u32 a;
    asm("{ .reg .u64 t; cvta.to.shared.u64 t, %1; cvt.u32.u64 %0, t; }"
        : "=r"(a) : "l"(p));
    return a;
}
__device__ __forceinline__ u32 bf2(float lo, float hi) {
    u32 r;  // first asm src -> upper half
    asm("cvt.rn.bf16x2.f32 %0, %1, %2;" : "=r"(r) : "f"(hi), "f"(lo));
    return r;
}
__device__ __forceinline__ void sts32(u32 a, u32 v) {
    asm volatile("st.shared.b32 [%0], %1;" :: "r"(a), "r"(v) : "memory");
}
__device__ __forceinline__ void sts64(u32 a, float x, float y) {
    asm volatile("st.shared.v2.f32 [%0], {%1,%2};" :: "r"(a), "f"(x), "f"(y) : "memory");
}
__device__ __forceinline__ float2 lds64(u32 a) {
    float2 r;
    asm volatile("ld.shared.v2.f32 {%0,%1}, [%2];" : "=f"(r.x), "=f"(r.y) : "r"(a));
    return r;
}
__device__ __forceinline__ void ldsm4t(u32* r, u32 a) {
    asm volatile("ldmatrix.sync.aligned.m8n8.x4.trans.shared.b16 {%0,%1,%2,%3}, [%4];"
        : "=r"(r[0]), "=r"(r[1]), "=r"(r[2]), "=r"(r[3]) : "r"(a));
}
__device__ __forceinline__ void ldsm2t(u32* r, u32 a) {
    asm volatile("ldmatrix.sync.aligned.m8n8.x2.trans.shared.b16 {%0,%1}, [%2];"
        : "=r"(r[0]), "=r"(r[1]) : "r"(a));
}
__device__ __forceinline__ void mma16816(float* d, const u32* a, const u32* b) {
    asm volatile(
        "mma.sync.aligned.m16n8k16.row.col.f32.bf16.bf16.f32 "
        "{%0,%1,%2,%3}, {%4,%5,%6,%7}, {%8,%9}, {%0,%1,%2,%3};"
        : "+f"(d[0]), "+f"(d[1]), "+f"(d[2]), "+f"(d[3])
        : "r"(a[0]), "r"(a[1]), "r"(a[2]), "r"(a[3]), "r"(b[0]), "r"(b[1]));
}

// swizzled byte offsets (rows 512B for P/H, 1024B for DS)
__device__ __forceinline__ u32 p_off(int row, int px) {      // bf16 [48][256]
    return (u32)(row * 512 + ((((px) >> 3) ^ (row & 7)) << 4) + ((px & 7) << 1));
}
__device__ __forceinline__ u32 h_off(int row, int px) {      // bf16 [128][256]
    return (u32)(row * 512 + ((((px) >> 3) ^ (row & 7)) << 4) + ((px & 7) << 1));
}
__device__ __forceinline__ u32 ds_off(int row, int px) {     // fp32 [16][256]
    return (u32)(row * 1024 + ((((px) >> 2) ^ (row & 7)) << 4) + ((px & 3) << 2));
}

__global__ __launch_bounds__(TPB)
void GCA_mma_kernel(const float* __restrict__ in, const float* __restrict__ w1,
                    const float* __restrict__ b1, const float* __restrict__ w2,
                    float* __restrict__ out)
{
    extern __shared__ char smem[];
    const u32 sb = smem_u32(smem);
    const int tid  = threadIdx.x;
    const int wid  = tid >> 5;
    const int lane = tid & 31;
    const int q    = lane & 3;
    const bool oddc = (lane & 4) != 0;     // handles col 2q+1 in pair exchanges

    // ---- stage transposed bf16 weights (one-time; region inside H) ----
    for (int i = tid; i < HID * PCH; i += TPB) {       // W1t[k][n] = w1[n*48+k]
        int n = i / PCH, k = i - n * PCH;
        *reinterpret_cast<__nv_bfloat16*>(smem + SM_W1T + k * 256 + n * 2) =
            __float2bfloat16(w1[i]);
    }
    for (int i = tid; i < HID * 16; i += TPB) {        // W2t[k][n], pad n 13..15
        int k = i >> 4, n = i & 15;
        float v = (n < OUTC) ? w2[n * HID + k] : 0.0f;
        *reinterpret_cast<__nv_bfloat16*>(smem + SM_W2T + i * 2) =
            __float2bfloat16(v);
    }
    __syncthreads();

    // ---- persistent weight fragments + bias ----
    u32 fb1[4][3][2];                    // layer1 B: n-tile j -> cols 32w+8j
    u32 fb2[2][8][2];                    // layer2 B: n-tile j -> cols 8j
    float bias[4][2];
#pragma unroll
    for (int j = 0; j < 4; ++j) {
#pragma unroll
        for (int kk = 0; kk < 3; ++kk)
            ldsm2t(fb1[j][kk],
                   sb + SM_W1T + (16 * kk + (lane & 15)) * 256 + (32 * wid + 8 * j) * 2);
        bias[j][0] = b1[32 * wid + 8 * j + 2 * q];
        bias[j][1] = b1[32 * wid + 8 * j + 2 * q + 1];
    }
#pragma unroll
    for (int j = 0; j < 2; ++j)
#pragma unroll
        for (int kk = 0; kk < 8; ++kk)
            ldsm2t(fb2[j][kk],
                   sb + SM_W2T + (16 * kk + (lane & 15)) * 32 + (8 * j) * 2);

    // ldmatrix.x4.trans lane addressing for K-major (col-major A) tiles
    const int lk = (lane & 7) + ((lane >> 4) << 3);    // k offset within 16
    const int lm = ((lane >> 3) & 1) << 3;             // m offset (0 or 8)

    for (int tile = blockIdx.x; tile < NTILES; tile += GRID) {
        const int bimg = tile >> 8;                    // batch
        const int y    = tile & 255;                   // image row
        const int rm = ((y - 1) & 255) << 8, r0 = y << 8, rp = ((y + 1) & 255) << 8;
        const float* bbase = in + ((size_t)bimg << 20);
        float* obase = out + ((size_t)bimg << 20);

        // ================= phase 1: perception (2 px/thread) =================
        {
            const int x0 = tid << 1;                   // even, no wrap on +1
            const int xm = (x0 - 1) & 255, x2 = (x0 + 2) & 255;
#pragma unroll
            for (int ch = 0; ch < Cz; ++ch) {
                const float* pc = bbase + (ch << 16);
                float2 a12 = *reinterpret_cast<const float2*>(pc + rm + x0);
                float2 b12 = *reinterpret_cast<const float2*>(pc + r0 + x0);
                float2 c12 = *reinterpret_cast<const float2*>(pc + rp + x0);
                float a0 = pc[rm + xm], a3 = pc[rm + x2];
                float b0 = pc[r0 + xm], b3 = pc[r0 + x2];
                float c0 = pc[rp + xm], c3 = pc[rp + x2];

                float gx0 = (a12.y - a0) + 2.0f * (b12.y - b0) + (c12.y - c0);
                float gx1 = (a3 - a12.x) + 2.0f * (b3 - b12.x) + (c3 - c12.x);
                float gy0 = (c0 + 2.0f * c12.x + c12.y) - (a0 + 2.0f * a12.x + a12.y);
                float gy1 = (c12.x + 2.0f * c12.y + c3) - (a12.x + 2.0f * a12.y + a3);

                sts32(sb + SM_P + p_off(ch,          x0), bf2(b12.x, b12.y));
                sts32(sb + SM_P + p_off(Cz + ch,     x0), bf2(gx0, gx1));
                sts32(sb + SM_P + p_off(2 * Cz + ch, x0), bf2(gy0, gy1));
                if (ch < 3)                              // exact state copy
                    *reinterpret_cast<float2*>(obase + (ch << 16) + r0 + x0) = b12;
            }
        }
        __syncthreads();

        // ================= phase 2: layer-1 (P -> H) =================
#pragma unroll 1
        for (int mt = 0; mt < 16; ++mt) {
            u32 a[3][4];
#pragma unroll
            for (int kk = 0; kk < 3; ++kk) {
                int krow = 16 * kk + lk;
                int pxc  = 16 * mt + lm;
                ldsm4t(a[kk], sb + SM_P + (u32)(krow * 512 +
                       (((pxc >> 3) ^ (krow & 7)) << 4)));
            }
#pragma unroll
            for (int n = 0; n < 4; ++n) {
                float c[4] = {0.f, 0.f, 0.f, 0.f};
#pragma unroll
                for (int kk = 0; kk < 3; ++kk) mma16816(c, a[kk], fb1[n][kk]);

                float h0 = fmaxf(c[0] + bias[n][0], 0.f);
                float h1 = fmaxf(c[1] + bias[n][1], 0.f);
                float h2 = fmaxf(c[2] + bias[n][0], 0.f);
                float h3 = fmaxf(c[3] + bias[n][1], 0.f);
                u32 v01 = bf2(h0, h1), v23 = bf2(h2, h3);
                u32 p01 = __shfl_xor_sync(0xffffffffu, v01, 4);
                u32 p23 = __shfl_xor_sync(0xffffffffu, v23, 4);
                u32 wa = oddc ? ((p01 >> 16) | (v01 & 0xFFFF0000u))
                              : ((v01 & 0xFFFFu) | (p01 << 16));
                u32 wb = oddc ? ((p23 >> 16) | (v23 & 0xFFFF0000u))
                              : ((v23 & 0xFFFFu) | (p23 << 16));
                int hid = 32 * wid + 8 * n + 2 * q + (oddc ? 1 : 0);
                int px  = 16 * mt + (lane >> 2);
                sts32(sb + SM_H + h_off(hid, px & ~1), wa);
                sts32(sb + SM_H + h_off(hid, (px + 8) & ~1), wb);
            }
        }
        __syncthreads();

        // ================= phase 3: layer-2 (H -> ds -> out) =================
#pragma unroll 1
        for (int mt = 0; mt < 4; ++mt) {
            const int m0 = 64 * wid + 16 * mt;
            float c2[2][4] = {{0.f,0.f,0.f,0.f},{0.f,0.f,0.f,0.f}};
#pragma unroll
            for (int kk = 0; kk < 8; ++kk) {
                u32 a2[4];
                int krow = 16 * kk + lk;
                int pxc  = m0 + lm;
                ldsm4t(a2, sb + SM_H + (u32)(krow * 512 +
                       (((pxc >> 3) ^ (krow & 7)) << 4)));
                mma16816(c2[0], a2, fb2[0][kk]);
                mma16816(c2[1], a2, fb2[1][kk]);
            }
#pragma unroll
            for (int n2 = 0; n2 < 2; ++n2)
#pragma unroll
                for (int hf = 0; hf < 2; ++hf) {
                    float dA = c2[n2][hf * 2], dB = c2[n2][hf * 2 + 1];
                    float pA = __shfl_xor_sync(0xffffffffu, dA, 4);
                    float pB = __shfl_xor_sync(0xffffffffu, dB, 4);
                    float lo = oddc ? pB : dA;
                    float hi = oddc ? dB : pA;
                    int chr = 3 + 8 * n2 + 2 * q + (oddc ? 1 : 0);
                    int px  = m0 + hf * 8 + (lane >> 2);
                    if (chr < 16)
                        sts64(sb + SM_DS + ds_off(chr, px & ~1), lo, hi);
                }
        }
        __syncwarp();

        // coalesced residual: out[ch] = in[ch] + ds[ch], ch 3..15
        {
            const int pxl = 64 * wid + 2 * lane;       // within tile
            const int gp  = tile * TILE + pxl;
            const int pix = gp & 65535;
#pragma unroll
            for (int ch = 3; ch < 16; ++ch) {
                float2 d = lds64(sb + SM_DS + ds_off(ch, pxl));
                const float2 s = *reinterpret_cast<const float2*>(
                    bbase + (ch << 16) + pix);
                float2 o;
                o.x = s.x + d.x;
                o.y = s.y + d.y;
                *reinterpret_cast<float2*>(obase + (ch << 16) + pix) = o;
            }
        }
        __syncthreads();   // P/H safe to overwrite next tile after this
    }
}

extern "C" void kernel_launch(void* const* d_in, const int* in_sizes, int n_in,
                              void* d_out, int out_size)
{
    const float* in = (const float*)d_in[0];
    const float* w1 = (const float*)d_in[1];
    const float* b1 = (const float*)d_in[2];
    const float* w2 = (const float*)d_in[3];
    float* out = (float*)d_out;

    cudaFuncSetAttribute(GCA_mma_kernel,
                         cudaFuncAttributeMaxDynamicSharedMemorySize, SM_TOT);
    GCA_mma_kernel<<<GRID, TPB, SM_TOT>>>(in, w1, b1, w2, out);
}

// round 7
// speedup vs baseline: 4.0709x; 1.3850x over previous
#include <cuda_runtime.h>
#include <cuda_bf16.h>
#include <cstdint>

// Fused GCA step via warp-level bf16 mma.sync, k-split layer-2 with
// accumulator->A-fragment reuse (no H materialization).
// B=16,C=16,H=256,W=256, HID=128, OUT_C=13, perception K=48.
#define Cz     16
#define HID    128
#define OUTC   13
#define PCH    48
#define TILE   256
#define NTILES 4096
#define TPB    256
#define GRID   296

// ---- shared memory (bytes) ----
#define SM_P   0            // P[48 ch][256 px] bf16 swizzled, 512B rows -> 24576
#define SM_DS  24576        // ds partials [4 kg][16 ch][256 px] fp32    -> 65536
#define SM_TOT 90112
// one-time weight staging overlaps the DS region (consumed before first DS write)
#define SM_W1T (SM_DS)              // W1t[48 k][128 n] bf16, 256B rows (12288)
#define SM_W2T (SM_DS + 12288)      // W2t[128 k][16 n]  bf16, 32B rows  (4096)

typedef unsigned int u32;

__device__ __forceinline__ u32 smem_u32(const void* p) {
    u32 a;
    asm("{ .reg .u64 t; cvta.to.shared.u64 t, %1; cvt.u32.u64 %0, t; }"
        : "=r"(a) : "l"(p));
    return a;
}
__device__ __forceinline__ u32 bf2(float lo, float hi) {
    u32 r;  // first asm src -> upper half
    asm("cvt.rn.bf16x2.f32 %0, %1, %2;" : "=r"(r) : "f"(hi), "f"(lo));
    return r;
}
__device__ __forceinline__ void sts64(u32 a, float x, float y) {
    asm volatile("st.shared.v2.f32 [%0], {%1,%2};" :: "r"(a), "f"(x), "f"(y) : "memory");
}
__device__ __forceinline__ float2 lds64(u32 a) {
    float2 r;
    asm volatile("ld.shared.v2.f32 {%0,%1}, [%2];" : "=f"(r.x), "=f"(r.y) : "r"(a));
    return r;
}
__device__ __forceinline__ void ldsm4t(u32* r, u32 a) {
    asm volatile("ldmatrix.sync.aligned.m8n8.x4.trans.shared.b16 {%0,%1,%2,%3}, [%4];"
        : "=r"(r[0]), "=r"(r[1]), "=r"(r[2]), "=r"(r[3]) : "r"(a));
}
__device__ __forceinline__ void ldsm2t(u32* r, u32 a) {
    asm volatile("ldmatrix.sync.aligned.m8n8.x2.trans.shared.b16 {%0,%1}, [%2];"
        : "=r"(r[0]), "=r"(r[1]) : "r"(a));
}
__device__ __forceinline__ void mma16816(float* d, const u32* a, const u32* b) {
    asm volatile(
        "mma.sync.aligned.m16n8k16.row.col.f32.bf16.bf16.f32 "
        "{%0,%1,%2,%3}, {%4,%5,%6,%7}, {%8,%9}, {%0,%1,%2,%3};"
        : "+f"(d[0]), "+f"(d[1]), "+f"(d[2]), "+f"(d[3])
        : "r"(a[0]), "r"(a[1]), "r"(a[2]), "r"(a[3]), "r"(b[0]), "r"(b[1]));
}

// swizzled byte offsets
__device__ __forceinline__ u32 p_off(int row, int px) {      // bf16 [48][256]
    return (u32)(row * 512 + ((((px) >> 3) ^ (row & 7)) << 4) + ((px & 7) << 1));
}
__device__ __forceinline__ u32 ds_off(int row, int px) {     // fp32 [16][256]
    return (u32)(row * 1024 + ((((px) >> 2) ^ (row & 7)) << 4) + ((px & 3) << 2));
}

__global__ __launch_bounds__(TPB, 2)
void GCA_mma2_kernel(const float* __restrict__ in, const float* __restrict__ w1,
                     const float* __restrict__ b1, const float* __restrict__ w2,
                     float* __restrict__ out)
{
    extern __shared__ char smem[];
    const u32 sb = smem_u32(smem);
    const int tid  = threadIdx.x;
    const int wid  = tid >> 5;
    const int lane = tid & 31;
    const int q    = lane & 3;
    const bool oddc = (lane & 4) != 0;
    const int kg   = wid & 3;          // k-group: hidden cols 32*kg..32*kg+31
    const int wpx  = wid >> 2;         // px half: 0 -> px 0..127, 1 -> 128..255

    // ---- stage transposed bf16 weights (region overlaps DS; one-time) ----
    for (int i = tid; i < HID * PCH; i += TPB) {        // W1t[k][n]
        int n = i / PCH, k = i - n * PCH;
        *reinterpret_cast<__nv_bfloat16*>(smem + SM_W1T + k * 256 + n * 2) =
            __float2bfloat16(w1[i]);
    }
    for (int i = tid; i < HID * 16; i += TPB) {         // W2t[k][n], pad n 13..15
        int k = i >> 4, n = i & 15;
        float v = (n < OUTC) ? w2[n * HID + k] : 0.0f;
        *reinterpret_cast<__nv_bfloat16*>(smem + SM_W2T + i * 2) =
            __float2bfloat16(v);
    }
    __syncthreads();

    // ---- persistent weight fragments + bias (per warp, k-group kg) ----
    u32 fb1[4][3][2];        // layer-1 B: n-tile j -> hid cols 32*kg + 8*j
    u32 fb2[2][2][2];        // layer-2 B: [kb][n2], k rows 32*kg+16*kb, cols 8*n2
    float bias[4][2];
#pragma unroll
    for (int j = 0; j < 4; ++j) {
#pragma unroll
        for (int kk = 0; kk < 3; ++kk)
            ldsm2t(fb1[j][kk],
                   sb + SM_W1T + (16 * kk + (lane & 15)) * 256 + (32 * kg + 8 * j) * 2);
        bias[j][0] = b1[32 * kg + 8 * j + 2 * q];
        bias[j][1] = b1[32 * kg + 8 * j + 2 * q + 1];
    }
#pragma unroll
    for (int kb = 0; kb < 2; ++kb)
#pragma unroll
        for (int n2 = 0; n2 < 2; ++n2)
            ldsm2t(fb2[kb][n2],
                   sb + SM_W2T + (32 * kg + 16 * kb + (lane & 15)) * 32 + 8 * n2 * 2);

    const int lk = (lane & 7) + ((lane >> 4) << 3);   // ldmatrix k offset
    const int lm = ((lane >> 3) & 1) << 3;            // ldmatrix m offset

    for (int tile = blockIdx.x; tile < NTILES; tile += GRID) {
        const int bimg = tile >> 8;
        const int y    = tile & 255;
        const int rm = ((y - 1) & 255) << 8, r0 = y << 8, rp = ((y + 1) & 255) << 8;
        const float* bbase = in + ((size_t)bimg << 20);
        float* obase = out + ((size_t)bimg << 20);

        // ============ phase 1: perception, 1 px/thread ============
        {
            const int x = tid;
            const int xm = (x - 1) & 255, xp = (x + 1) & 255;
#pragma unroll
            for (int ch = 0; ch < Cz; ++ch) {
                const float* pc = bbase + (ch << 16);
                float a0 = pc[rm + xm], a1 = pc[rm + x], a2 = pc[rm + xp];
                float b0 = pc[r0 + xm], bc = pc[r0 + x], b2 = pc[r0 + xp];
                float c0 = pc[rp + xm], c1 = pc[rp + x], c2 = pc[rp + xp];
                float gx = (a2 - a0) + 2.0f * (b2 - b0) + (c2 - c0);
                float gy = (c0 - a0) + 2.0f * (c1 - a1) + (c2 - a2);
                *reinterpret_cast<__nv_bfloat16*>(smem + SM_P + p_off(ch, x)) =
                    __float2bfloat16(bc);
                *reinterpret_cast<__nv_bfloat16*>(smem + SM_P + p_off(Cz + ch, x)) =
                    __float2bfloat16(gx);
                *reinterpret_cast<__nv_bfloat16*>(smem + SM_P + p_off(2 * Cz + ch, x)) =
                    __float2bfloat16(gy);
                if (ch < 3)                             // exact state copy
                    obase[(ch << 16) + r0 + x] = bc;
            }
        }
        __syncthreads();

        // ============ phase 2+3: fused MLP, k-split layer-2 ============
#pragma unroll 1
        for (int mt = 0; mt < 8; ++mt) {
            const int pxb = 128 * wpx + 16 * mt;

            u32 a[3][4];
#pragma unroll
            for (int kk = 0; kk < 3; ++kk) {
                int krow = 16 * kk + lk;
                int pxc  = pxb + lm;
                ldsm4t(a[kk], sb + SM_P + (u32)(krow * 512 +
                       (((pxc >> 3) ^ (krow & 7)) << 4)));
            }

            // layer-1: 4 n-tiles -> bias+ReLU -> bf16 A-frags for layer-2
            u32 a2f[2][4];
#pragma unroll
            for (int j = 0; j < 4; ++j) {
                float c[4] = {0.f, 0.f, 0.f, 0.f};
#pragma unroll
                for (int kk = 0; kk < 3; ++kk) mma16816(c, a[kk], fb1[j][kk]);
                float h0 = fmaxf(c[0] + bias[j][0], 0.f);
                float h1 = fmaxf(c[1] + bias[j][1], 0.f);
                float h2 = fmaxf(c[2] + bias[j][0], 0.f);
                float h3 = fmaxf(c[3] + bias[j][1], 0.f);
                a2f[j >> 1][(j & 1) * 2]     = bf2(h0, h1);   // rows 0-7 half
                a2f[j >> 1][(j & 1) * 2 + 1] = bf2(h2, h3);   // rows 8-15 half
            }

            // layer-2 partial over this warp's 32 hidden channels
            float c2[2][4] = {{0.f,0.f,0.f,0.f},{0.f,0.f,0.f,0.f}};
#pragma unroll
            for (int kb = 0; kb < 2; ++kb) {
                mma16816(c2[0], a2f[kb], fb2[kb][0]);
                mma16816(c2[1], a2f[kb], fb2[kb][1]);
            }

            // store ds partial (px-pair packing via xor-4 exchange)
            const u32 dsb = sb + SM_DS + (u32)kg * 16384u;
#pragma unroll
            for (int n2 = 0; n2 < 2; ++n2)
#pragma unroll
                for (int hf = 0; hf < 2; ++hf) {
                    float dA = c2[n2][hf * 2], dB = c2[n2][hf * 2 + 1];
                    float pA = __shfl_xor_sync(0xffffffffu, dA, 4);
                    float pB = __shfl_xor_sync(0xffffffffu, dB, 4);
                    float lo = oddc ? pB : dA;
                    float hi = oddc ? dB : pA;
                    int row = 8 * n2 + 2 * q + (oddc ? 1 : 0);   // out idx 0..15
                    int px  = pxb + hf * 8 + (lane >> 2);
                    sts64(dsb + ds_off(row, px & ~1), lo, hi);
                }
        }
        __syncthreads();

        // ============ phase 4: reduce 4 k-partials + residual ============
        {
            const int px0 = (tid & 127) << 1;
            const int cha = (tid < 128) ? 3 : 10;
            const int che = (tid < 128) ? 10 : 16;
            for (int ch = cha; ch < che; ++ch) {
                const int row = ch - 3;
                float2 s = *reinterpret_cast<const float2*>(
                    bbase + (ch << 16) + r0 + px0);
                float sx = s.x, sy = s.y;
#pragma unroll
                for (int g = 0; g < 4; ++g) {
                    float2 d = lds64(sb + SM_DS + (u32)g * 16384u + ds_off(row, px0));
                    sx += d.x; sy += d.y;
                }
                float2 o; o.x = sx; o.y = sy;
                *reinterpret_cast<float2*>(obase + (ch << 16) + r0 + px0) = o;
            }
        }
        __syncthreads();
    }
}

extern "C" void kernel_launch(void* const* d_in, const int* in_sizes, int n_in,
                              void* d_out, int out_size)
{
    const float* in = (const float*)d_in[0];
    const float* w1 = (const float*)d_in[1];
    const float* b1 = (const float*)d_in[2];
    const float* w2 = (const float*)d_in[3];
    float* out = (float*)d_out;

    cudaFuncSetAttribute(GCA_mma2_kernel,
                         cudaFuncAttributeMaxDynamicSharedMemorySize, SM_TOT);
    GCA_mma2_kernel<<<GRID, TPB, SM_TOT>>>(in, w1, b1, w2, out);
}

// round 11
// speedup vs baseline: 4.7303x; 1.1620x over previous
#include <cuda_runtime.h>
#include <cuda_bf16.h>
#include <cstdint>

// Fused GCA step via warp-level bf16 mma.sync; row-pair tiles, 2px/thread
// perception, k-split layer-2 with accumulator->A reuse, bf16 ds partials.
// B=16,C=16,H=256,W=256, HID=128, OUT_C=13, perception K=48.
#define Cz     16
#define HID    128
#define OUTC   13
#define NPAIRS 2048        // 16 images * 128 row pairs
#define TPB    256
#define GRID   296
#define PCH    48

// ---- shared memory (bytes) ----
#define SM_PA  0            // P_A[48][256] bf16 swizzled 512B rows -> 24576
#define SM_PB  24576        // P_B                                   -> 24576
#define SM_DS  49152        // ds partials [4 kg][16 ch][256 px] bf16 -> 32768
#define SM_TOT 81920
// one-time weight staging overlaps DS (consumed before first DS write)
#define SM_W1T (SM_DS)              // W1t[48][128] bf16 256B rows (12288)
#define SM_W2T (SM_DS + 12288)      // W2t[128][16] bf16 32B rows   (4096)

typedef unsigned int u32;

__device__ __forceinline__ u32 smem_u32(const void* p) {
    u32 a;
    asm("{ .reg .u64 t; cvta.to.shared.u64 t, %1; cvt.u32.u64 %0, t; }"
        : "=r"(a) : "l"(p));
    return a;
}
__device__ __forceinline__ u32 bf2(float lo, float hi) {
    u32 r;  // first asm src -> upper half
    asm("cvt.rn.bf16x2.f32 %0, %1, %2;" : "=r"(r) : "f"(hi), "f"(lo));
    return r;
}
__device__ __forceinline__ void sts32(u32 a, u32 v) {
    asm volatile("st.shared.b32 [%0], %1;" :: "r"(a), "r"(v) : "memory");
}
__device__ __forceinline__ u32 lds32(u32 a) {
    u32 r;
    asm volatile("ld.shared.b32 %0, [%1];" : "=r"(r) : "r"(a));
    return r;
}
__device__ __forceinline__ void ldsm4t(u32* r, u32 a) {
    asm volatile("ldmatrix.sync.aligned.m8n8.x4.trans.shared.b16 {%0,%1,%2,%3}, [%4];"
        : "=r"(r[0]), "=r"(r[1]), "=r"(r[2]), "=r"(r[3]) : "r"(a));
}
__device__ __forceinline__ void ldsm2t(u32* r, u32 a) {
    asm volatile("ldmatrix.sync.aligned.m8n8.x2.trans.shared.b16 {%0,%1}, [%2];"
        : "=r"(r[0]), "=r"(r[1]) : "r"(a));
}
__device__ __forceinline__ void mma16816(float* d, const u32* a, const u32* b) {
    asm volatile(
        "mma.sync.aligned.m16n8k16.row.col.f32.bf16.bf16.f32 "
        "{%0,%1,%2,%3}, {%4,%5,%6,%7}, {%8,%9}, {%0,%1,%2,%3};"
        : "+f"(d[0]), "+f"(d[1]), "+f"(d[2]), "+f"(d[3])
        : "r"(a[0]), "r"(a[1]), "r"(a[2]), "r"(a[3]), "r"(b[0]), "r"(b[1]));
}

// swizzled byte offsets (512B rows, bf16 [rows][256 px])
__device__ __forceinline__ u32 p_off(int row, int px) {
    return (u32)(row * 512 + ((((px) >> 3) ^ (row & 7)) << 4) + ((px & 7) << 1));
}
#define ds_off p_off      // ds is also bf16 [16][256] swizzled

__global__ __launch_bounds__(TPB, 2)
void GCA_mma3_kernel(const float* __restrict__ in, const float* __restrict__ w1,
                     const float* __restrict__ b1, const float* __restrict__ w2,
                     float* __restrict__ out)
{
    extern __shared__ char smem[];
    const u32 sb = smem_u32(smem);
    const int tid  = threadIdx.x;
    const int wid  = tid >> 5;
    const int lane = tid & 31;
    const int q    = lane & 3;
    const bool oddc = (lane & 4) != 0;
    const int kg   = wid & 3;          // hidden k-group: cols 32*kg..32*kg+31
    const int wpx  = wid >> 2;         // px half within the row

    // ---- stage transposed bf16 weights (overlaps DS; one-time) ----
    for (int i = tid; i < HID * PCH; i += TPB) {
        int n = i / PCH, k = i - n * PCH;
        *reinterpret_cast<__nv_bfloat16*>(smem + SM_W1T + k * 256 + n * 2) =
            __float2bfloat16(w1[i]);
    }
    for (int i = tid; i < HID * 16; i += TPB) {
        int k = i >> 4, n = i & 15;
        float v = (n < OUTC) ? w2[n * HID + k] : 0.0f;
        *reinterpret_cast<__nv_bfloat16*>(smem + SM_W2T + i * 2) =
            __float2bfloat16(v);
    }
    __syncthreads();

    // ---- persistent weight fragments + bias (per warp k-group) ----
    u32 fb1[4][3][2];
    u32 fb2[2][2][2];
    float bias[4][2];
#pragma unroll
    for (int j = 0; j < 4; ++j) {
#pragma unroll
        for (int kk = 0; kk < 3; ++kk)
            ldsm2t(fb1[j][kk],
                   sb + SM_W1T + (16 * kk + (lane & 15)) * 256 + (32 * kg + 8 * j) * 2);
        bias[j][0] = b1[32 * kg + 8 * j + 2 * q];
        bias[j][1] = b1[32 * kg + 8 * j + 2 * q + 1];
    }
#pragma unroll
    for (int kb = 0; kb < 2; ++kb)
#pragma unroll
        for (int n2 = 0; n2 < 2; ++n2)
            ldsm2t(fb2[kb][n2],
                   sb + SM_W2T + (32 * kg + 16 * kb + (lane & 15)) * 32 + 8 * n2 * 2);
    __syncthreads();      // weights consumed; DS region free

    const int lk = (lane & 7) + ((lane >> 4) << 3);
    const int lm = ((lane >> 3) & 1) << 3;

    for (int pair = blockIdx.x; pair < NPAIRS; pair += GRID) {
        const int bimg = pair >> 7;
        const int y0   = (pair & 127) << 1;
        const float* bbase = in + ((size_t)bimg << 20);
        float* obase = out + ((size_t)bimg << 20);

        // ===== phase 1: perception, row pair, 2 px/thread =====
        {
            const int h  = tid >> 7;              // 0 -> row y0, 1 -> row y0+1
            const int y  = y0 + h;
            const int x0 = (tid & 127) << 1;
            const int xm = (x0 - 1) & 255, x2 = (x0 + 2) & 255;
            const int rm = ((y - 1) & 255) << 8, r0 = y << 8,
                      rp = ((y + 1) & 255) << 8;
            const u32 pb = sb + (h ? SM_PB : SM_PA);
#pragma unroll
            for (int ch = 0; ch < Cz; ++ch) {
                const float* pc = bbase + (ch << 16);
                float2 a12 = *reinterpret_cast<const float2*>(pc + rm + x0);
                float2 b12 = *reinterpret_cast<const float2*>(pc + r0 + x0);
                float2 c12 = *reinterpret_cast<const float2*>(pc + rp + x0);
                float a0 = pc[rm + xm], a3 = pc[rm + x2];
                float b0 = pc[r0 + xm], b3 = pc[r0 + x2];
                float c0 = pc[rp + xm], c3 = pc[rp + x2];

                float gx0 = (a12.y - a0) + 2.0f * (b12.y - b0) + (c12.y - c0);
                float gx1 = (a3 - a12.x) + 2.0f * (b3 - b12.x) + (c3 - c12.x);
                float gy0 = (c0 + 2.0f * c12.x + c12.y) - (a0 + 2.0f * a12.x + a12.y);
                float gy1 = (c12.x + 2.0f * c12.y + c3) - (a12.x + 2.0f * a12.y + a3);

                sts32(pb + p_off(ch,          x0), bf2(b12.x, b12.y));
                sts32(pb + p_off(Cz + ch,     x0), bf2(gx0, gx1));
                sts32(pb + p_off(2 * Cz + ch, x0), bf2(gy0, gy1));
                if (ch < 3)                        // exact state copy
                    *reinterpret_cast<float2*>(obase + (ch << 16) + r0 + x0) = b12;
            }
        }
        __syncthreads();

        // ===== phases 2-4 for each row of the pair =====
#pragma unroll 1
        for (int rs = 0; rs < 2; ++rs) {
            const u32 pb = sb + (rs ? SM_PB : SM_PA);
            const int y  = y0 + rs;
            const int r0 = y << 8;

            // ---- fused MLP, k-split layer-2 ----
#pragma unroll 1
            for (int mt = 0; mt < 8; ++mt) {
                const int pxb = 128 * wpx + 16 * mt;
                u32 a[3][4];
#pragma unroll
                for (int kk = 0; kk < 3; ++kk) {
                    int krow = 16 * kk + lk;
                    int pxc  = pxb + lm;
                    ldsm4t(a[kk], pb + (u32)(krow * 512 +
                           (((pxc >> 3) ^ (krow & 7)) << 4)));
                }

                u32 a2f[2][4];
#pragma unroll
                for (int j = 0; j < 4; ++j) {
                    float c[4] = {0.f, 0.f, 0.f, 0.f};
#pragma unroll
                    for (int kk = 0; kk < 3; ++kk) mma16816(c, a[kk], fb1[j][kk]);
                    float h0 = fmaxf(c[0] + bias[j][0], 0.f);
                    float h1 = fmaxf(c[1] + bias[j][1], 0.f);
                    float h2 = fmaxf(c[2] + bias[j][0], 0.f);
                    float h3 = fmaxf(c[3] + bias[j][1], 0.f);
                    a2f[j >> 1][(j & 1) * 2]     = bf2(h0, h1);
                    a2f[j >> 1][(j & 1) * 2 + 1] = bf2(h2, h3);
                }

                float c2[2][4] = {{0.f,0.f,0.f,0.f},{0.f,0.f,0.f,0.f}};
#pragma unroll
                for (int kb = 0; kb < 2; ++kb) {
                    mma16816(c2[0], a2f[kb], fb2[kb][0]);
                    mma16816(c2[1], a2f[kb], fb2[kb][1]);
                }

                const u32 dsb = sb + SM_DS + (u32)kg * 8192u;
#pragma unroll
                for (int n2 = 0; n2 < 2; ++n2)
#pragma unroll
                    for (int hf = 0; hf < 2; ++hf) {
                        float dA = c2[n2][hf * 2], dB = c2[n2][hf * 2 + 1];
                        float pA = __shfl_xor_sync(0xffffffffu, dA, 4);
                        float pB = __shfl_xor_sync(0xffffffffu, dB, 4);
                        float lo = oddc ? pB : dA;
                        float hi = oddc ? dB : pA;
                        int row = 8 * n2 + 2 * q + (oddc ? 1 : 0);   // 0..15
                        int px  = pxb + hf * 8 + (lane >> 2);
                        if (row < 13)
                            sts32(dsb + ds_off(row, px & ~1), bf2(lo, hi));
                    }
            }
            __syncthreads();

            // ---- reduce 4 k-partials + residual ----
            {
                const int px0 = (tid & 127) << 1;
                const int cha = (tid < 128) ? 3 : 10;
                const int che = (tid < 128) ? 10 : 16;
                for (int ch = cha; ch < che; ++ch) {
                    const int row = ch - 3;
                    float2 s = *reinterpret_cast<const float2*>(
                        bbase + (ch << 16) + r0 + px0);
                    float sx = s.x, sy = s.y;
#pragma unroll
                    for (int g = 0; g < 4; ++g) {
                        u32 w = lds32(sb + SM_DS + (u32)g * 8192u + ds_off(row, px0));
                        sx += __uint_as_float(w << 16);
                        sy += __uint_as_float(w & 0xFFFF0000u);
                    }
                    float2 o; o.x = sx; o.y = sy;
                    *reinterpret_cast<float2*>(obase + (ch << 16) + r0 + px0) = o;
                }
            }
            __syncthreads();
        }
    }
}

extern "C" void kernel_launch(void* const* d_in, const int* in_sizes, int n_in,
                              void* d_out, int out_size)
{
    const float* in = (const float*)d_in[0];
    const float* w1 = (const float*)d_in[1];
    const float* b1 = (const float*)d_in[2];
    const float* w2 = (const float*)d_in[3];
    float* out = (float*)d_out;

    cudaFuncSetAttribute(GCA_mma3_kernel,
                         cudaFuncAttributeMaxDynamicSharedMemorySize, SM_TOT);
    GCA_mma3_kernel<<<GRID, TPB, SM_TOT>>>(in, w1, b1, w2, out);
}

// round 12
// speedup vs baseline: 4.9723x; 1.0512x over previous
#include <cuda_runtime.h>
#include <cuda_bf16.h>
#include <cstdint>

// Fused GCA step via warp-level bf16 mma.sync; row-pair tiles,
// channel-split 4-row perception, k-split layer-2 (acc->A reuse),
// kg-pair-packed bf16 ds partials (no shfl), lds64 reduce.
// B=16,C=16,H=256,W=256, HID=128, OUT_C=13, perception K=48.
#define Cz     16
#define HID    128
#define OUTC   13
#define NPAIRS 2048
#define TPB    256
#define GRID   296
#define PCH    48

// ---- shared memory (bytes) ----
#define SM_PA  0            // P_A[48][256] bf16 swizzled 512B rows -> 24576
#define SM_PB  24576        // P_B                                   -> 24576
#define SM_DS  49152        // ds partials [2 grp][16 ch][256 px] u32(=2 bf16 kg) -> 32768
#define SM_TOT 81920
// one-time weight staging overlaps DS (consumed before first DS write)
#define SM_W1T (SM_DS)              // W1t[48][128] bf16 256B rows (12288)
#define SM_W2T (SM_DS + 12288)      // W2t[128][16] bf16 32B rows   (4096)

typedef unsigned int u32;

__device__ __forceinline__ u32 smem_u32(const void* p) {
    u32 a;
    asm("{ .reg .u64 t; cvta.to.shared.u64 t, %1; cvt.u32.u64 %0, t; }"
        : "=r"(a) : "l"(p));
    return a;
}
__device__ __forceinline__ u32 bf2(float lo, float hi) {
    u32 r;  // first asm src -> upper half
    asm("cvt.rn.bf16x2.f32 %0, %1, %2;" : "=r"(r) : "f"(hi), "f"(lo));
    return r;
}
__device__ __forceinline__ void sts32(u32 a, u32 v) {
    asm volatile("st.shared.b32 [%0], %1;" :: "r"(a), "r"(v) : "memory");
}
__device__ __forceinline__ void sts16(u32 a, u32 v) {
    asm volatile("{ .reg .b16 h; cvt.u16.u32 h, %1; st.shared.b16 [%0], h; }"
                 :: "r"(a), "r"(v) : "memory");
}
__device__ __forceinline__ uint2 lds64u(u32 a) {
    uint2 r;
    asm volatile("ld.shared.v2.b32 {%0,%1}, [%2];" : "=r"(r.x), "=r"(r.y) : "r"(a));
    return r;
}
__device__ __forceinline__ void ldsm4t(u32* r, u32 a) {
    asm volatile("ldmatrix.sync.aligned.m8n8.x4.trans.shared.b16 {%0,%1,%2,%3}, [%4];"
        : "=r"(r[0]), "=r"(r[1]), "=r"(r[2]), "=r"(r[3]) : "r"(a));
}
__device__ __forceinline__ void ldsm2t(u32* r, u32 a) {
    asm volatile("ldmatrix.sync.aligned.m8n8.x2.trans.shared.b16 {%0,%1}, [%2];"
        : "=r"(r[0]), "=r"(r[1]) : "r"(a));
}
__device__ __forceinline__ void mma16816(float* d, const u32* a, const u32* b) {
    asm volatile(
        "mma.sync.aligned.m16n8k16.row.col.f32.bf16.bf16.f32 "
        "{%0,%1,%2,%3}, {%4,%5,%6,%7}, {%8,%9}, {%0,%1,%2,%3};"
        : "+f"(d[0]), "+f"(d[1]), "+f"(d[2]), "+f"(d[3])
        : "r"(a[0]), "r"(a[1]), "r"(a[2]), "r"(a[3]), "r"(b[0]), "r"(b[1]));
}

// P: bf16 [rows][256 px], 512B rows, XOR-swizzled 16B groups
__device__ __forceinline__ u32 p_off(int row, int px) {
    return (u32)(row * 512 + ((((px) >> 3) ^ (row & 7)) << 4) + ((px & 7) << 1));
}
// ds: u32 [16 ch][256 px] per group, swizzled: bank-safe for 4ch x 8px stores
__device__ __forceinline__ u32 ds2_off(int ch, int px) {
    return (u32)(ch * 1024 + ((((px) >> 2) ^ (ch & 7)) << 4) + ((px & 3) << 2));
}

__global__ __launch_bounds__(TPB, 2)
void GCA_mma4_kernel(const float* __restrict__ in, const float* __restrict__ w1,
                     const float* __restrict__ b1, const float* __restrict__ w2,
                     float* __restrict__ out)
{
    extern __shared__ char smem[];
    const u32 sb = smem_u32(smem);
    const int tid  = threadIdx.x;
    const int wid  = tid >> 5;
    const int lane = tid & 31;
    const int q    = lane & 3;
    const int kg   = wid & 3;          // hidden k-group: cols 32*kg..32*kg+31
    const int wpx  = wid >> 2;         // px half within the row

    // ---- stage transposed bf16 weights (overlaps DS; one-time) ----
    for (int i = tid; i < HID * PCH; i += TPB) {
        int n = i / PCH, k = i - n * PCH;
        *reinterpret_cast<__nv_bfloat16*>(smem + SM_W1T + k * 256 + n * 2) =
            __float2bfloat16(w1[i]);
    }
    for (int i = tid; i < HID * 16; i += TPB) {
        int k = i >> 4, n = i & 15;
        float v = (n < OUTC) ? w2[n * HID + k] : 0.0f;
        *reinterpret_cast<__nv_bfloat16*>(smem + SM_W2T + i * 2) =
            __float2bfloat16(v);
    }
    __syncthreads();

    // ---- persistent weight fragments + bias (per warp k-group) ----
    u32 fb1[4][3][2];
    u32 fb2[2][2][2];
    float bias[4][2];
#pragma unroll
    for (int j = 0; j < 4; ++j) {
#pragma unroll
        for (int kk = 0; kk < 3; ++kk)
            ldsm2t(fb1[j][kk],
                   sb + SM_W1T + (16 * kk + (lane & 15)) * 256 + (32 * kg + 8 * j) * 2);
        bias[j][0] = b1[32 * kg + 8 * j + 2 * q];
        bias[j][1] = b1[32 * kg + 8 * j + 2 * q + 1];
    }
#pragma unroll
    for (int kb = 0; kb < 2; ++kb)
#pragma unroll
        for (int n2 = 0; n2 < 2; ++n2)
            ldsm2t(fb2[kb][n2],
                   sb + SM_W2T + (32 * kg + 16 * kb + (lane & 15)) * 32 + 8 * n2 * 2);
    __syncthreads();      // weights consumed; DS region free

    const int lk = (lane & 7) + ((lane >> 4) << 3);
    const int lm = ((lane >> 3) & 1) << 3;

    for (int pair = blockIdx.x; pair < NPAIRS; pair += GRID) {
        const int bimg = pair >> 7;
        const int y0   = (pair & 127) << 1;
        const float* bbase = in + ((size_t)bimg << 20);
        float* obase = out + ((size_t)bimg << 20);

        // ===== phase 1: perception — ch-split, 4 input rows, both outputs =====
        {
            const int cg = tid >> 7;               // 0: ch 0-7, 1: ch 8-15
            const int x0 = (tid & 127) << 1;       // even, +1 never wraps
            const int xm = (x0 - 1) & 255, x2 = (x0 + 2) & 255;
            const int rA = ((y0 - 1) & 255) << 8;  // row y0-1
            const int rB = y0 << 8;                // row y0
            const int rC = (y0 + 1) << 8;          // row y0+1  (y0<=254)
            const int rD = ((y0 + 2) & 255) << 8;  // row y0+2
#pragma unroll
            for (int c8 = 0; c8 < 8; ++c8) {
                const int ch = cg * 8 + c8;
                const float* pc = bbase + (ch << 16);
                float2 vA = *reinterpret_cast<const float2*>(pc + rA + x0);
                float2 vB = *reinterpret_cast<const float2*>(pc + rB + x0);
                float2 vC = *reinterpret_cast<const float2*>(pc + rC + x0);
                float2 vD = *reinterpret_cast<const float2*>(pc + rD + x0);
                float aL = pc[rA + xm], aR = pc[rA + x2];
                float bL = pc[rB + xm], bR = pc[rB + x2];
                float cL = pc[rC + xm], cR = pc[rC + x2];
                float dL = pc[rD + xm], dR = pc[rD + x2];

                // row y0 (A,B,C)
                float gx0 = (vA.y - aL) + 2.0f * (vB.y - bL) + (vC.y - cL);
                float gx1 = (aR - vA.x) + 2.0f * (bR - vB.x) + (cR - vC.x);
                float gy0 = (cL + 2.0f * vC.x + vC.y) - (aL + 2.0f * vA.x + vA.y);
                float gy1 = (vC.x + 2.0f * vC.y + cR) - (vA.x + 2.0f * vA.y + aR);
                sts32(sb + SM_PA + p_off(ch,          x0), bf2(vB.x, vB.y));
                sts32(sb + SM_PA + p_off(Cz + ch,     x0), bf2(gx0, gx1));
                sts32(sb + SM_PA + p_off(2 * Cz + ch, x0), bf2(gy0, gy1));

                // row y0+1 (B,C,D)
                float hx0 = (vB.y - bL) + 2.0f * (vC.y - cL) + (vD.y - dL);
                float hx1 = (bR - vB.x) + 2.0f * (cR - vC.x) + (dR - vD.x);
                float hy0 = (dL + 2.0f * vD.x + vD.y) - (bL + 2.0f * vB.x + vB.y);
                float hy1 = (vD.x + 2.0f * vD.y + dR) - (vB.x + 2.0f * vB.y + bR);
                sts32(sb + SM_PB + p_off(ch,          x0), bf2(vC.x, vC.y));
                sts32(sb + SM_PB + p_off(Cz + ch,     x0), bf2(hx0, hx1));
                sts32(sb + SM_PB + p_off(2 * Cz + ch, x0), bf2(hy0, hy1));

                if (ch < 3) {                      // exact state copy, both rows
                    *reinterpret_cast<float2*>(obase + (ch << 16) + rB + x0) = vB;
                    *reinterpret_cast<float2*>(obase + (ch << 16) + rC + x0) = vC;
                }
            }
        }
        __syncthreads();

        // ===== phases 2-4 for each row of the pair =====
#pragma unroll 1
        for (int rs = 0; rs < 2; ++rs) {
            const u32 pb = sb + (rs ? SM_PB : SM_PA);
            const int r0 = (y0 + rs) << 8;

            // ---- fused MLP, k-split layer-2 ----
#pragma unroll 1
            for (int mt = 0; mt < 8; ++mt) {
                const int pxb = 128 * wpx + 16 * mt;
                u32 a[3][4];
#pragma unroll
                for (int kk = 0; kk < 3; ++kk) {
                    int krow = 16 * kk + lk;
                    int pxc  = pxb + lm;
                    ldsm4t(a[kk], pb + (u32)(krow * 512 +
                           (((pxc >> 3) ^ (krow & 7)) << 4)));
                }

                u32 a2f[2][4];
#pragma unroll
                for (int j = 0; j < 4; ++j) {
                    float c[4] = {0.f, 0.f, 0.f, 0.f};
#pragma unroll
                    for (int kk = 0; kk < 3; ++kk) mma16816(c, a[kk], fb1[j][kk]);
                    float h0 = fmaxf(c[0] + bias[j][0], 0.f);
                    float h1 = fmaxf(c[1] + bias[j][1], 0.f);
                    float h2 = fmaxf(c[2] + bias[j][0], 0.f);
                    float h3 = fmaxf(c[3] + bias[j][1], 0.f);
                    a2f[j >> 1][(j & 1) * 2]     = bf2(h0, h1);
                    a2f[j >> 1][(j & 1) * 2 + 1] = bf2(h2, h3);
                }

                float c2[2][4] = {{0.f,0.f,0.f,0.f},{0.f,0.f,0.f,0.f}};
#pragma unroll
                for (int kb = 0; kb < 2; ++kb) {
                    mma16816(c2[0], a2f[kb], fb2[kb][0]);
                    mma16816(c2[1], a2f[kb], fb2[kb][1]);
                }

                // store ds partial: bf16 into kg-pair packed u32 words
                const u32 dsb = sb + SM_DS + (u32)(kg >> 1) * 16384u
                                + (u32)(kg & 1) * 2u;
#pragma unroll
                for (int n2 = 0; n2 < 2; ++n2)
#pragma unroll
                    for (int ci = 0; ci < 4; ++ci) {
                        int ch = 8 * n2 + 2 * q + (ci & 1);
                        int px = pxb + (lane >> 2) + ((ci >> 1) << 3);
                        u32 hb = bf2(0.0f, c2[n2][ci]) >> 16;  // bf16 bits
                        sts16(dsb + ds2_off(ch, px), hb);
                    }
            }
            __syncthreads();

            // ---- reduce 2 packed groups (4 kg) + residual ----
            {
                const int px0 = (tid & 127) << 1;
                const int cha = (tid < 128) ? 3 : 10;
                const int che = (tid < 128) ? 10 : 16;
                for (int ch = cha; ch < che; ++ch) {
                    const int row = ch - 3;
                    float2 s = *reinterpret_cast<const float2*>(
                        bbase + (ch << 16) + r0 + px0);
                    float sx = s.x, sy = s.y;
#pragma unroll
                    for (int g = 0; g < 2; ++g) {
                        uint2 w = lds64u(sb + SM_DS + (u32)g * 16384u
                                         + ds2_off(row, px0));
                        sx += __uint_as_float(w.x << 16);
                        sx += __uint_as_float(w.x & 0xFFFF0000u);
                        sy += __uint_as_float(w.y << 16);
                        sy += __uint_as_float(w.y & 0xFFFF0000u);
                    }
                    float2 o; o.x = sx; o.y = sy;
                    *reinterpret_cast<float2*>(obase + (ch << 16) + r0 + px0) = o;
                }
            }
            __syncthreads();
        }
    }
}

extern "C" void kernel_launch(void* const* d_in, const int* in_sizes, int n_in,
                              void* d_out, int out_size)
{
    const float* in = (const float*)d_in[0];
    const float* w1 = (const float*)d_in[1];
    const float* b1 = (const float*)d_in[2];
    const float* w2 = (const float*)d_in[3];
    float* out = (float*)d_out;

    cudaFuncSetAttribute(GCA_mma4_kernel,
                         cudaFuncAttributeMaxDynamicSharedMemorySize, SM_TOT);
    GCA_mma4_kernel<<<GRID, TPB, SM_TOT>>>(in, w1, b1, w2, out);
}